// round 7
// baseline (speedup 1.0000x reference)
#include <cuda_runtime.h>
#include <cstdint>

#define B_SZ  2
#define GQ    32
#define HDIM  128
#define NH    8
#define DK    16
#define SLEN  4096
#define STILE 8
#define NT    256

typedef unsigned long long u64;

// SMEM (u64 units), total 14464 u64 = 115712 B -> 2 CTAs/SM:
//  sQ/xc [0,2048)     overlay:
//     Q view: u64[(d*4+sp)*32 + g]        written B4->B1, read B1->B2
//     xc view: u64[(sp*16+d)*32 + g]      written B2.5->B3, read B3->B4
//  sK   [2048,4096)   float[f*128 + d*8 + s]  (16 KB tile)
//  sV   [4096,6144)   same
//  sL   [6144,10240)  u64[(sp*32+f)*32 + g]   logits sums over h
//  sA   [10240,14336) same                    attn sums over h
//  sSum [14336,14464) u64[sp*32 + g]  softmax totals via red.shared.add.f32
//     (2 adds per slot -> order-independent bits; zeroed post-B2.5)
#define SQ_U64   0
#define SK_U64   2048
#define SV_U64   4096
#define SL_U64   6144
#define SA_U64   10240
#define SSUM_U64 14336
#define SM_U64_TOTAL 14464
#define SM_BYTES (SM_U64_TOTAL * 8)   // 115712

// ---- packed f32x2 + misc helpers ----
__device__ __forceinline__ u64 pk2(float lo, float hi) {
    u64 r; asm("mov.b64 %0, {%1, %2};" : "=l"(r) : "f"(lo), "f"(hi)); return r;
}
__device__ __forceinline__ void up2(u64 v, float& lo, float& hi) {
    asm("mov.b64 {%0, %1}, %2;" : "=f"(lo), "=f"(hi) : "l"(v));
}
__device__ __forceinline__ u64 fma2(u64 a, u64 b, u64 c) {
    u64 d; asm("fma.rn.f32x2 %0, %1, %2, %3;" : "=l"(d) : "l"(a), "l"(b), "l"(c)); return d;
}
__device__ __forceinline__ u64 add2(u64 a, u64 b) {
    u64 d; asm("add.rn.f32x2 %0, %1, %2;" : "=l"(d) : "l"(a), "l"(b)); return d;
}
__device__ __forceinline__ u64 mul2(u64 a, u64 b) {
    u64 d; asm("mul.rn.f32x2 %0, %1, %2;" : "=l"(d) : "l"(a), "l"(b)); return d;
}
__device__ __forceinline__ float ex2a(float x) {
    float r; asm("ex2.approx.ftz.f32 %0, %1;" : "=f"(r) : "f"(x)); return r;
}
__device__ __forceinline__ float rcpa(float x) {
    float r; asm("rcp.approx.ftz.f32 %0, %1;" : "=f"(r) : "f"(x)); return r;
}
__device__ __forceinline__ void cp_async16(void* dst, const void* src) {
    unsigned sdst = (unsigned)__cvta_generic_to_shared(dst);
    asm volatile("cp.async.cg.shared.global [%0], [%1], 16;" :: "r"(sdst), "l"(src));
}
__device__ __forceinline__ void cp_commit() {
    asm volatile("cp.async.commit_group;" ::: "memory");
}
__device__ __forceinline__ void cp_wait0() {
    asm volatile("cp.async.wait_group 0;" ::: "memory");
}
__device__ __forceinline__ void red_shared_f32(void* p, float v) {
    unsigned sa = (unsigned)__cvta_generic_to_shared(p);
    asm volatile("red.shared.add.f32 [%0], %1;" :: "r"(sa), "f"(v) : "memory");
}

// stage a 32x16x8-float tile (K or V): 1024 16B chunks, 4 per thread (NT=256)
__device__ __forceinline__ void stage_async(float* dst, const float* src0, int t) {
    #pragma unroll
    for (int i = 0; i < 4; ++i) {
        int c = t + NT * i;                     // chunk id 0..1023
        int r = c >> 1;                         // row = g*16 + d
        const float* src = src0 + ((size_t)(r >> 4) * HDIM + (r & 15)) * SLEN + 4 * (c & 1);
        cp_async16(dst + 4 * c, src);
    }
}

// Q staging by threads t<128 (lane=g row, w4=d offset)
__device__ __forceinline__ void load_q_ldg(ulonglong2* qA, ulonglong2* qB,
                                           const float* gq, int lane, int w4) {
    #pragma unroll
    for (int i = 0; i < 4; ++i) {
        int d = w4 + 4 * i;
        const float* src = gq + ((size_t)lane * HDIM + d) * SLEN;
        qA[i] = *(const ulonglong2*)(src);
        qB[i] = *(const ulonglong2*)(src + 4);
    }
}
__device__ __forceinline__ void sts_q(u64* sQ, const ulonglong2* qA, const ulonglong2* qB,
                                      int lane, int w4) {
    #pragma unroll
    for (int i = 0; i < 4; ++i) {
        int d = w4 + 4 * i;
        u64* dst = sQ + (size_t)(d * 4) * 32 + lane;
        dst[0] = qA[i].x; dst[32] = qA[i].y; dst[64] = qB[i].x; dst[96] = qB[i].y;
    }
}

__global__ void __launch_bounds__(NT, 2)
sdpa_group_kernel(const float* __restrict__ q, const float* __restrict__ k,
                  const float* __restrict__ v, float* __restrict__ out)
{
    extern __shared__ u64 sm[];
    u64*   sQ   = sm + SQ_U64;     // also xc (time-disjoint)
    u64*   xc   = sm + SQ_U64;
    float* sK   = (float*)(sm + SK_U64);
    float* sV   = (float*)(sm + SV_U64);
    u64*   sL   = sm + SL_U64;
    u64*   sA   = sm + SA_U64;
    u64*   sSum = sm + SSUM_U64;

    const int t    = threadIdx.x;
    const int lane = t & 31;
    const int warp = t >> 5;
    const int g    = lane;
    const int sp   = warp & 3;           // s-pair: s = 2sp, 2sp+1
    const int fh   = warp >> 2;          // f-half: f in [16*fh, 16*fh+16)
    const int f0   = fh * 16;
    const int s0   = blockIdx.x * STILE;
    const int b    = blockIdx.y;
    const bool qstager = (t < 128);
    const int w4 = warp & 3;

    const size_t base = (size_t)b * (GQ * HDIM) * SLEN + (size_t)s0;
    const float L2E = 1.4426950408889634f;

    // ---- prologue: async K(0)+V(0), LDG Q(0), zero sums+sSum, STS Q(0) ----
    stage_async(sK, k + base, t);
    stage_async(sV, v + base, t);
    cp_commit();
    ulonglong2 qA[4], qB[4];
    if (qstager) load_q_ldg(qA, qB, q + base, lane, w4);
    #pragma unroll 4
    for (int i = t; i < 8320; i += NT) sL[i] = 0ull;     // sL,sA,sSum contiguous
    if (qstager) sts_q(sQ, qA, qB, lane, w4);

    const u64 sc = pk2(0.25f * L2E, 0.25f * L2E);        // dk^-0.5 * log2(e)

    #pragma unroll 1
    for (int h = 0; h < NH; ++h) {
        cp_wait0();              // K(h), V(h) arrived
        __syncthreads();         // B1: tiles + Q(h) visible

        // early LDG of Q(h+1)
        if (qstager && h < NH - 1)
            load_q_ldg(qA, qB, q + base + (size_t)(h + 1) * DK * SLEN, lane, w4);

        // ---- qv = Q[g, :, s-pair] * scale ----
        u64 qv[DK];
        {
            const u64* qp = sQ + sp * 32 + g;
            #pragma unroll
            for (int d = 0; d < DK; ++d) qv[d] = mul2(qp[d * 128], sc);
        }

        // ---- logits for this f-half (log2 domain) ----
        u64 lg[16];
        #pragma unroll
        for (int fi = 0; fi < 16; ++fi) {
            const float* kb = sK + (f0 + fi) * 128 + 2 * sp;
            u64 a0 = mul2(qv[0], *(const u64*)(kb));
            u64 a1 = mul2(qv[1], *(const u64*)(kb + 8));
            #pragma unroll
            for (int d = 2; d < DK; d += 2) {
                a0 = fma2(qv[d],     *(const u64*)(kb + 8 * d),     a0);
                a1 = fma2(qv[d + 1], *(const u64*)(kb + 8 * d + 8), a1);
            }
            lg[fi] = add2(a0, a1);
        }

        // ---- accumulate logits sums ----
        u64* Lr = sL + (sp * 32 + f0) * 32 + g;
        #pragma unroll
        for (int fi = 0; fi < 16; ++fi) {
            u64* p = Lr + fi * 32;
            *p = add2(*p, lg[fi]);
        }

        // ---- exp2 + half-sum, contribute via red.shared (2 adds/slot) ----
        #pragma unroll
        for (int fi = 0; fi < 16; ++fi) {
            float a, bb; up2(lg[fi], a, bb);
            lg[fi] = pk2(ex2a(a), ex2a(bb));
        }
        {
            u64 ss[8];
            #pragma unroll
            for (int i = 0; i < 8; ++i) ss[i] = add2(lg[2 * i], lg[2 * i + 1]);
            #pragma unroll
            for (int i = 0; i < 4; ++i) ss[i] = add2(ss[2 * i], ss[2 * i + 1]);
            u64 psum = add2(add2(ss[0], ss[1]), add2(ss[2], ss[3]));
            float p0, p1; up2(psum, p0, p1);
            float* slot = (float*)(sSum + sp * 32 + g);
            red_shared_f32(slot,     p0);
            red_shared_f32(slot + 1, p1);
        }

        __syncthreads();         // B2: logits done (sK, sQ dead), sums complete

        // prefetch K(h+1)
        if (h < NH - 1) {
            stage_async(sK, k + base + (size_t)(h + 1) * DK * SLEN, t);
            cp_commit();
        }

        // ---- total sum -> rn; normalize; accumulate attn sums ----
        float sum0, sum1; up2(sSum[sp * 32 + g], sum0, sum1);
        const u64 rn = pk2(rcpa(sum0), rcpa(sum1));

        u64* Ar = sA + (sp * 32 + f0) * 32 + g;
        #pragma unroll
        for (int fi = 0; fi < 16; ++fi) {
            lg[fi] = mul2(lg[fi], rn);
            u64* p = Ar + fi * 32;
            *p = add2(*p, lg[fi]);
        }

        // ---- x partial over this f-half ----
        u64 xv[DK];
        {
            const float* vb0 = sV + f0 * 128 + 2 * sp;
            #pragma unroll
            for (int d = 0; d < DK; ++d)
                xv[d] = mul2(lg[0], *(const u64*)(vb0 + 8 * d));
            #pragma unroll
            for (int fi = 1; fi < 16; ++fi) {
                const float* vb = sV + (f0 + fi) * 128 + 2 * sp;
                #pragma unroll
                for (int d = 0; d < DK; ++d)
                    xv[d] = fma2(lg[fi], *(const u64*)(vb + 8 * d), xv[d]);
            }
        }

        __syncthreads();         // B2.5: sV dead, sSum reads done

        // prefetch V(h+1); zero sSum for next h
        if (h < NH - 1) {
            stage_async(sV, v + base + (size_t)(h + 1) * DK * SLEN, t);
            cp_commit();
        }
        if (t < 128) sSum[t] = 0ull;

        // ---- post partner's d-half partials into xc (== sQ region, Q dead) ----
        {
            const int dout = (1 - fh) * 8;
            u64* xr = xc + (sp * 16) * 32 + g;
            #pragma unroll
            for (int j = 0; j < 8; ++j)
                xr[(dout + j) * 32] = xv[dout + j];
        }
        __syncthreads();         // B3: partials posted

        // ---- combine + store x for own d-half ----
        {
            const int dmy = fh * 8;
            const u64* xr = xc + (sp * 16 + dmy) * 32 + g;
            float* xo = out + (((size_t)(b * GQ + g) * HDIM) + (size_t)h * DK + dmy) * SLEN
                            + (size_t)s0 + 2 * sp;
            #pragma unroll
            for (int j = 0; j < 8; ++j) {
                u64 r = add2(xv[dmy + j], xr[j * 32]);
                *(u64*)(xo + (size_t)j * SLEN) = r;
            }
        }
        __syncthreads();         // B4: partial reads done -> xc region free for Q(h+1)

        if (qstager && h < NH - 1) sts_q(sQ, qA, qB, lane, w4);
    }

    // ---- writeout head means ----
    __syncthreads();
    const size_t AOFF = (size_t)B_SZ * GQ * HDIM * SLEN;       // 33554432
    const size_t LOFF = AOFF + (size_t)B_SZ * GQ * GQ * SLEN;  // 41943040
    const u64 cA = pk2(0.125f, 0.125f);
    const float lsc = 0.125f / L2E;                            // undo log2-domain
    const u64 cL = pk2(lsc, lsc);
    #pragma unroll
    for (int i = 0; i < 4; ++i) {
        int r  = t + NT * i;      // 0..1023
        int f  = r & 31;
        int gg = r >> 5;
        size_t o = ((size_t)(b * GQ + gg) * GQ + f) * SLEN + (size_t)s0;
        #pragma unroll
        for (int sp2 = 0; sp2 < 4; ++sp2) {
            int idx = (sp2 * 32 + f) * 32 + gg;
            *(u64*)(out + AOFF + o + 2 * sp2) = mul2(sA[idx], cA);
            *(u64*)(out + LOFF + o + 2 * sp2) = mul2(sL[idx], cL);
        }
    }
}

extern "C" void kernel_launch(void* const* d_in, const int* in_sizes, int n_in,
                              void* d_out, int out_size)
{
    const float* q = (const float*)d_in[0];
    const float* k = (const float*)d_in[1];
    const float* v = (const float*)d_in[2];
    float* out = (float*)d_out;

    cudaFuncSetAttribute(sdpa_group_kernel,
                         cudaFuncAttributeMaxDynamicSharedMemorySize, SM_BYTES);

    dim3 grid(SLEN / STILE, B_SZ);
    sdpa_group_kernel<<<grid, NT, SM_BYTES>>>(q, k, v, out);
}

// round 8
// speedup vs baseline: 1.1878x; 1.1878x over previous
#include <cuda_runtime.h>
#include <cstdint>

#define B_SZ  2
#define GQ    32
#define HDIM  128
#define NH    8
#define DK    16
#define SLEN  4096
#define STILE 8
#define NT    256

typedef unsigned long long u64;

// SMEM (u64 units), total 14464 u64 = 115712 B -> 2 CTAs/SM:
//  sQ   [0,2048)      u64[(d*4+sp)*32 + g]        (Q tile; dead after B2)
//  sK   [2048,4096)   float[f*128 + d*8 + s]      (K tile; dead after B2)
//    eX  = [0,4096)   u64[(sp*32+f)*32 + g]       probs exchange (B2->B4)
//    xSt = [0,2048)   u64[(sp*16+d)*32 + g]       x staging (B4->B5)
//  sV   [4096,6144)   float[f*128 + d*8 + s]      (V tile; dead after B4)
//  sL   [6144,10240)  u64[(sp*32+f)*32 + g]       logits sums over h
//  sA   [10240,14336) same                        attn sums over h
//  sSum [14336,14464) u64[sp*32 + g]              softmax totals (red.shared,
//                     exactly 2 adds/slot -> deterministic; zeroed post-B3)
#define SQ_U64   0
#define SK_U64   2048
#define SV_U64   4096
#define SL_U64   6144
#define SA_U64   10240
#define SSUM_U64 14336
#define SM_U64_TOTAL 14464
#define SM_BYTES (SM_U64_TOTAL * 8)   // 115712

// ---- packed f32x2 + misc helpers ----
__device__ __forceinline__ u64 pk2(float lo, float hi) {
    u64 r; asm("mov.b64 %0, {%1, %2};" : "=l"(r) : "f"(lo), "f"(hi)); return r;
}
__device__ __forceinline__ void up2(u64 v, float& lo, float& hi) {
    asm("mov.b64 {%0, %1}, %2;" : "=f"(lo), "=f"(hi) : "l"(v));
}
__device__ __forceinline__ u64 fma2(u64 a, u64 b, u64 c) {
    u64 d; asm("fma.rn.f32x2 %0, %1, %2, %3;" : "=l"(d) : "l"(a), "l"(b), "l"(c)); return d;
}
__device__ __forceinline__ u64 add2(u64 a, u64 b) {
    u64 d; asm("add.rn.f32x2 %0, %1, %2;" : "=l"(d) : "l"(a), "l"(b)); return d;
}
__device__ __forceinline__ u64 mul2(u64 a, u64 b) {
    u64 d; asm("mul.rn.f32x2 %0, %1, %2;" : "=l"(d) : "l"(a), "l"(b)); return d;
}
__device__ __forceinline__ float ex2a(float x) {
    float r; asm("ex2.approx.ftz.f32 %0, %1;" : "=f"(r) : "f"(x)); return r;
}
__device__ __forceinline__ float rcpa(float x) {
    float r; asm("rcp.approx.ftz.f32 %0, %1;" : "=f"(r) : "f"(x)); return r;
}
__device__ __forceinline__ void cp_async16(void* dst, const void* src) {
    unsigned sdst = (unsigned)__cvta_generic_to_shared(dst);
    asm volatile("cp.async.cg.shared.global [%0], [%1], 16;" :: "r"(sdst), "l"(src));
}
__device__ __forceinline__ void cp_commit() {
    asm volatile("cp.async.commit_group;" ::: "memory");
}
__device__ __forceinline__ void cp_wait0() {
    asm volatile("cp.async.wait_group 0;" ::: "memory");
}
__device__ __forceinline__ void red_shared_f32(void* p, float v) {
    unsigned sa = (unsigned)__cvta_generic_to_shared(p);
    asm volatile("red.shared.add.f32 [%0], %1;" :: "r"(sa), "f"(v) : "memory");
}

// stage a 32x16x8-float tile (K or V): 1024 16B chunks, 4 per thread (NT=256)
__device__ __forceinline__ void stage_async(float* dst, const float* src0, int t) {
    #pragma unroll
    for (int i = 0; i < 4; ++i) {
        int c = t + NT * i;                     // chunk id 0..1023
        int r = c >> 1;                         // row = g*16 + d
        const float* src = src0 + ((size_t)(r >> 4) * HDIM + (r & 15)) * SLEN + 4 * (c & 1);
        cp_async16(dst + 4 * c, src);
    }
}

// Q staging by threads t<128 (lane=g row, w4=d offset)
__device__ __forceinline__ void load_q_ldg(ulonglong2* qA, ulonglong2* qB,
                                           const float* gq, int lane, int w4) {
    #pragma unroll
    for (int i = 0; i < 4; ++i) {
        int d = w4 + 4 * i;
        const float* src = gq + ((size_t)lane * HDIM + d) * SLEN;
        qA[i] = *(const ulonglong2*)(src);
        qB[i] = *(const ulonglong2*)(src + 4);
    }
}
__device__ __forceinline__ void sts_q(u64* sQ, const ulonglong2* qA, const ulonglong2* qB,
                                      int lane, int w4) {
    #pragma unroll
    for (int i = 0; i < 4; ++i) {
        int d = w4 + 4 * i;
        u64* dst = sQ + (size_t)(d * 4) * 32 + lane;
        dst[0] = qA[i].x; dst[32] = qA[i].y; dst[64] = qB[i].x; dst[96] = qB[i].y;
    }
}

__global__ void __launch_bounds__(NT, 2)
sdpa_group_kernel(const float* __restrict__ q, const float* __restrict__ k,
                  const float* __restrict__ v, float* __restrict__ out)
{
    extern __shared__ u64 sm[];
    u64*   sQ   = sm + SQ_U64;
    u64*   eX   = sm + SQ_U64;     // probs exchange (sQ+sK overlay, B2->B4)
    u64*   xSt  = sm + SQ_U64;     // x staging (sQ overlay, B4->B5)
    float* sK   = (float*)(sm + SK_U64);
    float* sV   = (float*)(sm + SV_U64);
    u64*   sL   = sm + SL_U64;
    u64*   sA   = sm + SA_U64;
    u64*   sSum = sm + SSUM_U64;

    const int t    = threadIdx.x;
    const int lane = t & 31;
    const int warp = t >> 5;
    const int g    = lane;
    const int sp   = warp & 3;           // s-pair: s = 2sp, 2sp+1
    const int fh   = warp >> 2;          // f-half: f in [16*fh, 16*fh+16)
    const int f0   = fh * 16;
    const int d0   = fh * 8;             // d-half owned in the x phase
    const int s0   = blockIdx.x * STILE;
    const int b    = blockIdx.y;
    const bool qstager = (t < 128);
    const int w4 = warp & 3;

    const size_t base = (size_t)b * (GQ * HDIM) * SLEN + (size_t)s0;
    const float L2E = 1.4426950408889634f;

    // ---- prologue ----
    stage_async(sK, k + base, t);
    stage_async(sV, v + base, t);
    cp_commit();
    ulonglong2 qA[4], qB[4];
    if (qstager) load_q_ldg(qA, qB, q + base, lane, w4);
    #pragma unroll 4
    for (int i = t; i < 8320; i += NT) sL[i] = 0ull;     // sL,sA,sSum contiguous
    if (qstager) sts_q(sQ, qA, qB, lane, w4);

    const u64 sc = pk2(0.25f * L2E, 0.25f * L2E);        // dk^-0.5 * log2(e)

    #pragma unroll 1
    for (int h = 0; h < NH; ++h) {
        cp_wait0();              // K(h), V(h) arrived
        __syncthreads();         // B1: tiles + Q(h) visible

        // early LDG of Q(h+1), held in regs until after B5
        if (qstager && h < NH - 1)
            load_q_ldg(qA, qB, q + base + (size_t)(h + 1) * DK * SLEN, lane, w4);

        // ---- qv = Q[g, :, s-pair] * scale ----
        u64 qv[DK];
        {
            const u64* qp = sQ + sp * 32 + g;
            #pragma unroll
            for (int d = 0; d < DK; ++d) qv[d] = mul2(qp[d * 128], sc);
        }

        // ---- logits for this f-half (log2 domain) ----
        u64 lg[16];
        #pragma unroll
        for (int fi = 0; fi < 16; ++fi) {
            const float* kb = sK + (f0 + fi) * 128 + 2 * sp;
            u64 a0 = mul2(qv[0], *(const u64*)(kb));
            u64 a1 = mul2(qv[1], *(const u64*)(kb + 8));
            #pragma unroll
            for (int d = 2; d < DK; d += 2) {
                a0 = fma2(qv[d],     *(const u64*)(kb + 8 * d),     a0);
                a1 = fma2(qv[d + 1], *(const u64*)(kb + 8 * d + 8), a1);
            }
            lg[fi] = add2(a0, a1);
        }

        // ---- accumulate logits sums ----
        u64* Lr = sL + (sp * 32 + f0) * 32 + g;
        #pragma unroll
        for (int fi = 0; fi < 16; ++fi) {
            u64* p = Lr + fi * 32;
            *p = add2(*p, lg[fi]);
        }

        // ---- exp2 + half-sum via red.shared (exactly 2 adds/slot) ----
        #pragma unroll
        for (int fi = 0; fi < 16; ++fi) {
            float a, bb; up2(lg[fi], a, bb);
            lg[fi] = pk2(ex2a(a), ex2a(bb));
        }
        {
            u64 ss[8];
            #pragma unroll
            for (int i = 0; i < 8; ++i) ss[i] = add2(lg[2 * i], lg[2 * i + 1]);
            #pragma unroll
            for (int i = 0; i < 4; ++i) ss[i] = add2(ss[2 * i], ss[2 * i + 1]);
            u64 psum = add2(add2(ss[0], ss[1]), add2(ss[2], ss[3]));
            float p0, p1; up2(psum, p0, p1);
            float* slot = (float*)(sSum + sp * 32 + g);
            red_shared_f32(slot,     p0);
            red_shared_f32(slot + 1, p1);
        }

        __syncthreads();         // B2: logits done (sQ, sK dead), sums complete

        // ---- rn; normalize; accumulate attn sums; post probs to eX ----
        {
            float sum0, sum1; up2(sSum[sp * 32 + g], sum0, sum1);
            const u64 rn = pk2(rcpa(sum0), rcpa(sum1));
            u64* Ar = sA + (sp * 32 + f0) * 32 + g;
            u64* Er = eX + (sp * 32 + f0) * 32 + g;
            #pragma unroll
            for (int fi = 0; fi < 16; ++fi) {
                lg[fi] = mul2(lg[fi], rn);
                u64* p = Ar + fi * 32;
                *p = add2(*p, lg[fi]);
                Er[fi * 32] = lg[fi];
            }
        }
        __syncthreads();         // B3: probs posted, sSum reads done

        if (t < 128) sSum[t] = 0ull;   // reset for next h (next adds after B1)

        // ---- x for own d-half over ALL f: xv[j] = sum_f p_f V[f][d0+j] ----
        u64 xv[8];
        {
            const u64* Ep = eX + (sp * 32) * 32 + g;
            u64 e0 = Ep[0];
            const float* vb0 = sV + d0 * 8 + 2 * sp;     // f = 0
            #pragma unroll
            for (int j = 0; j < 8; ++j)
                xv[j] = mul2(e0, *(const u64*)(vb0 + 8 * j));
            #pragma unroll
            for (int f = 1; f < GQ; ++f) {
                u64 e = Ep[f * 32];
                const float* vb = sV + f * 128 + d0 * 8 + 2 * sp;
                #pragma unroll
                for (int j = 0; j < 8; ++j)
                    xv[j] = fma2(e, *(const u64*)(vb + 8 * j), xv[j]);
            }
        }
        __syncthreads();         // B4: x-FMAs done everywhere (eX, sV, sK dead)

        // prefetch K(h+1), V(h+1)
        if (h < NH - 1) {
            stage_async(sK, k + base + (size_t)(h + 1) * DK * SLEN, t);
            stage_async(sV, v + base + (size_t)(h + 1) * DK * SLEN, t);
            cp_commit();
        }

        // ---- stage x into xSt [(sp*16+d)*32+g] (2-wavefront STS) ----
        {
            u64* xr = xSt + (sp * 16 + d0) * 32 + g;
            #pragma unroll
            for (int j = 0; j < 8; ++j)
                xr[j * 32] = xv[j];
        }
        __syncthreads();         // B4.5: x staged

        // ---- cooperative coalesced STG: row (g,d) = 32B, 2 lanes per row ----
        #pragma unroll
        for (int i = 0; i < 4; ++i) {
            int u    = t + NT * i;        // 0..1023 units of 16B
            int r    = u >> 1;            // row id: d = r>>5, g2 = r&31
            int half = u & 1;             // 16B half of the row
            int dd   = r >> 5;
            int g2   = r & 31;
            u64 lo = xSt[((2 * half)     * 16 + dd) * 32 + g2];
            u64 hi = xSt[((2 * half + 1) * 16 + dd) * 32 + g2];
            float* dst = out + ((size_t)((b * GQ + g2) * HDIM) + (size_t)h * DK + dd) * SLEN
                             + (size_t)s0 + 4 * half;
            ulonglong2 val; val.x = lo; val.y = hi;
            *(ulonglong2*)dst = val;
        }
        __syncthreads();         // B5: staging reads done -> region free for Q(h+1)

        if (qstager && h < NH - 1) sts_q(sQ, qA, qB, lane, w4);
    }

    // ---- writeout head means ----
    __syncthreads();
    const size_t AOFF = (size_t)B_SZ * GQ * HDIM * SLEN;       // 33554432
    const size_t LOFF = AOFF + (size_t)B_SZ * GQ * GQ * SLEN;  // 41943040
    const u64 cA = pk2(0.125f, 0.125f);
    const float lsc = 0.125f / L2E;                            // undo log2-domain
    const u64 cL = pk2(lsc, lsc);
    #pragma unroll
    for (int i = 0; i < 4; ++i) {
        int r  = t + NT * i;      // 0..1023
        int f  = r & 31;
        int gg = r >> 5;
        size_t o = ((size_t)(b * GQ + gg) * GQ + f) * SLEN + (size_t)s0;
        #pragma unroll
        for (int sp2 = 0; sp2 < 4; ++sp2) {
            int idx = (sp2 * 32 + f) * 32 + gg;
            *(u64*)(out + AOFF + o + 2 * sp2) = mul2(sA[idx], cA);
            *(u64*)(out + LOFF + o + 2 * sp2) = mul2(sL[idx], cL);
        }
    }
}

extern "C" void kernel_launch(void* const* d_in, const int* in_sizes, int n_in,
                              void* d_out, int out_size)
{
    const float* q = (const float*)d_in[0];
    const float* k = (const float*)d_in[1];
    const float* v = (const float*)d_in[2];
    float* out = (float*)d_out;

    cudaFuncSetAttribute(sdpa_group_kernel,
                         cudaFuncAttributeMaxDynamicSharedMemorySize, SM_BYTES);

    dim3 grid(SLEN / STILE, B_SZ);
    sdpa_group_kernel<<<grid, NT, SM_BYTES>>>(q, k, v, out);
}